// round 10
// baseline (speedup 1.0000x reference)
#include <cuda_runtime.h>
#include <cstdint>

#define NC         100000
#define FEAT       256
#define BATCH      16384
#define F4         64                          // FEAT / 4
#define THREADS    256
#define WPB        8
#define CNT_BLOCKS 64
#define ACC_BLOCKS (BATCH / WPB)               // 2048 (one warp per sample)
#define CPB        256
#define CLS_BLOCKS ((NC + CPB - 1) / CPB)      // 391

// contrib_c = Q - 1.9602 D + 0.9801 E - (0.0199/n) ||s||^2
//   Q = sum ||x_i||^2, D = c.s, E = n ||c||^2   (t = 0.99c + 0.01 s/n)
#define A_D 1.9602f
#define A_E 0.9801f
#define A_S 0.0199f

// Scratch — zero at module load; every replay restores the all-zero invariant.
__device__ float4   g_scal[NC];                 // {Q, D, E, n}  (1.6 MB)
__device__ float4   g_sums[(size_t)NC * F4];    // rows used ONLY for n>=2 classes
__device__ float    g_loss;
__device__ unsigned g_done;

__device__ __forceinline__ void red_add_v4(float* addr, float4 v) {
    asm volatile("red.global.add.v4.f32 [%0], {%1, %2, %3, %4};"
                 :: "l"(addr), "f"(v.x), "f"(v.y), "f"(v.z), "f"(v.w)
                 : "memory");
}
__device__ __forceinline__ void red_add_f32(float* addr, float v) {
    asm volatile("red.global.add.f32 [%0], %1;" :: "l"(addr), "f"(v) : "memory");
}
__device__ __forceinline__ float dot4(float4 a, float4 b) {
    return a.x*b.x + a.y*b.y + a.z*b.z + a.w*b.w;
}

// ---------------------------------------------------------------------------
// Branch A1: per-class counts (float, exact below 2^24).
// ---------------------------------------------------------------------------
__global__ __launch_bounds__(THREADS) void countk(const int* __restrict__ label) {
    for (int i = blockIdx.x * THREADS + threadIdx.x; i < BATCH;
         i += CNT_BLOCKS * THREADS)
        red_add_f32(&g_scal[label[i]].w, 1.0f);
}

// ---------------------------------------------------------------------------
// Branch A2 (after countk): vector-RED x rows into g_sums for multi classes
// only (~16% of samples do work; rest exit after one broadcast load).
// ---------------------------------------------------------------------------
__global__ __launch_bounds__(THREADS) void rowred(const float* __restrict__ x,
                                                  const int* __restrict__ label) {
    int w    = (blockIdx.x * THREADS + threadIdx.x) >> 5;   // sample id
    int lane = threadIdx.x & 31;
    int c    = label[w];
    if (g_scal[c].w < 2.f) return;              // broadcast load of count

    const float4* xr = reinterpret_cast<const float4*>(x) + (size_t)w * F4;
    float4 v0 = xr[lane], v1 = xr[lane + 32];
    float* srow = reinterpret_cast<float*>(g_sums + (size_t)c * F4);
    red_add_v4(srow + lane * 4,        v0);
    red_add_v4(srow + (lane + 32) * 4, v1);
}

// ---------------------------------------------------------------------------
// Branch B (concurrent with A1+A2): Q/D/E scalars. One warp per sample;
// reads x row + gathered center row; REDs into g_scal.x/.y/.z (disjoint from
// .w used by branch A).
// ---------------------------------------------------------------------------
__global__ __launch_bounds__(THREADS) void qde(const float* __restrict__ x,
                                               const float* __restrict__ center,
                                               const int* __restrict__ label) {
    int w    = (blockIdx.x * THREADS + threadIdx.x) >> 5;
    int lane = threadIdx.x & 31;
    int c    = label[w];

    const float4* xr = reinterpret_cast<const float4*>(x)      + (size_t)w * F4;
    const float4* cr = reinterpret_cast<const float4*>(center) + (size_t)c * F4;
    float4 v0 = xr[lane], v1 = xr[lane + 32];
    float4 c0 = cr[lane], c1 = cr[lane + 32];

    float q = dot4(v0, v0) + dot4(v1, v1);
    float d = dot4(v0, c0) + dot4(v1, c1);
    float e = dot4(c0, c0) + dot4(c1, c1);
    #pragma unroll
    for (int o = 16; o > 0; o >>= 1) {
        q += __shfl_down_sync(0xFFFFFFFFu, q, o);
        d += __shfl_down_sync(0xFFFFFFFFu, d, o);
        e += __shfl_down_sync(0xFFFFFFFFu, e, o);
    }
    if (lane == 0) {
        float* base = reinterpret_cast<float*>(&g_scal[c]);
        red_add_f32(base + 0, q);
        red_add_f32(base + 1, d);
        red_add_f32(base + 2, e);
    }
}

// ---------------------------------------------------------------------------
// Join: coalesced scan of g_scal; multi classes get a warp stage for ||s||^2
// + row zeroing; g_loss atomic + last-block writes out. Invariants restored.
// ---------------------------------------------------------------------------
__global__ __launch_bounds__(THREADS) void classpass(float* __restrict__ out) {
    __shared__ int   s_m;
    __shared__ int   s_cls[CPB];
    __shared__ float s_n[CPB];
    __shared__ float s_wsum[WPB];

    int tid  = threadIdx.x;
    int lane = tid & 31;
    int wid  = tid >> 5;

    if (tid == 0) s_m = 0;
    __syncthreads();

    float contrib = 0.f;
    int c = blockIdx.x * CPB + tid;
    if (c < NC) {
        float4 sc = g_scal[c];                  // coalesced 16B
        if (sc.w > 0.f) {
            contrib = sc.x - A_D * sc.y + A_E * sc.z;
            if (sc.w == 1.f) {
                contrib -= A_S * sc.x;          // ||s||^2 == Q for n = 1
            } else {
                int p = atomicAdd(&s_m, 1);
                s_cls[p] = c;
                s_n[p]   = sc.w;
            }
            g_scal[c] = make_float4(0.f, 0.f, 0.f, 0.f);    // restore invariant
        }
    }
    __syncthreads();

    int m = s_m;                                // ~3 multi classes per block
    for (int i = wid; i < m; i += WPB) {
        int cc = s_cls[i];
        float4* srow = g_sums + (size_t)cc * F4;
        float4 s0 = srow[lane], s1 = srow[lane + 32];
        float4 z = make_float4(0.f, 0.f, 0.f, 0.f);
        srow[lane] = z;                         // restore invariant
        srow[lane + 32] = z;
        float ss = dot4(s0, s0) + dot4(s1, s1);
        #pragma unroll
        for (int o = 16; o > 0; o >>= 1)
            ss += __shfl_down_sync(0xFFFFFFFFu, ss, o);
        if (lane == 0) contrib -= A_S * ss / s_n[i];
    }

    #pragma unroll
    for (int o = 16; o > 0; o >>= 1)
        contrib += __shfl_down_sync(0xFFFFFFFFu, contrib, o);
    if (lane == 0) s_wsum[wid] = contrib;
    __syncthreads();

    if (tid == 0) {
        float b = 0.f;
        #pragma unroll
        for (int i = 0; i < WPB; i++) b += s_wsum[i];
        atomicAdd(&g_loss, b);
        __threadfence();
        if (atomicAdd(&g_done, 1u) == (unsigned)(gridDim.x - 1)) {
            out[0] = __ldcg(&g_loss) * (1.f / ((float)BATCH * (float)FEAT));
            g_loss = 0.f;                       // restore invariants
            g_done = 0u;
        }
    }
}

extern "C" void kernel_launch(void* const* d_in, const int* in_sizes, int n_in,
                              void* d_out, int out_size) {
    const float* x      = (const float*)d_in[0];   // batch_feature [16384, 256] f32
    const int*   label  = (const int*)d_in[1];     // batch_label   [16384] int32
    const float* center = (const float*)d_in[2];   // center_feature[100000, 256] f32
    float* out = (float*)d_out;

    // One-time host-side resources (no device memory involved).
    static cudaStream_t s2 = nullptr;
    static cudaEvent_t  evFork = nullptr, evJoin = nullptr;
    if (s2 == nullptr) {
        cudaStreamCreateWithFlags(&s2, cudaStreamNonBlocking);
        cudaEventCreateWithFlags(&evFork, cudaEventDisableTiming);
        cudaEventCreateWithFlags(&evJoin, cudaEventDisableTiming);
    }

    // Fork: branch B (qde) runs concurrently with branch A (countk -> rowred).
    cudaEventRecord(evFork, 0);
    cudaStreamWaitEvent(s2, evFork, 0);

    qde<<<ACC_BLOCKS, THREADS, 0, s2>>>(x, center, label);   // branch B (heavy)

    countk<<<CNT_BLOCKS, THREADS>>>(label);                  // branch A
    rowred<<<ACC_BLOCKS, THREADS>>>(x, label);

    // Join, then the scan + finalize.
    cudaEventRecord(evJoin, s2);
    cudaStreamWaitEvent(0, evJoin, 0);
    classpass<<<CLS_BLOCKS, THREADS>>>(out);
}

// round 11
// speedup vs baseline: 1.0748x; 1.0748x over previous
#include <cuda_runtime.h>
#include <cstdint>

#define NC         100000
#define FEAT       256
#define BATCH      16384
#define F4         64                          // FEAT / 4
#define THREADS    256
#define WPB        8
#define ACC_BLOCKS (BATCH / WPB)               // 2048 (one warp per sample)
#define CPB        256                         // classes scanned per block
#define CLS_BLOCKS ((NC + CPB - 1) / CPB)      // 391

// contrib_c = Q - 1.9602 D + 0.9801 E - (0.0199/n) ||s||^2
//   Q = sum ||x_i||^2, D = c.s, E = n ||c||^2   (t = 0.99c + 0.01 s/n)
#define A_D 1.9602f
#define A_E 0.9801f
#define A_S 0.0199f

// Scratch — zero at module load; every replay restores the all-zero invariant.
__device__ float4   g_scal[NC];                 // {Q, D, E, n}  (1.6 MB)
__device__ float4   g_sums[(size_t)NC * F4];    // per-class sums (~102 MB)
__device__ float    g_loss;
__device__ unsigned g_done;

__device__ __forceinline__ void red_add_v4(float* addr, float4 v) {
    asm volatile("red.global.add.v4.f32 [%0], {%1, %2, %3, %4};"
                 :: "l"(addr), "f"(v.x), "f"(v.y), "f"(v.z), "f"(v.w)
                 : "memory");
}
__device__ __forceinline__ void red_add_f32(float* addr, float v) {
    asm volatile("red.global.add.f32 [%0], %1;" :: "l"(addr), "f"(v) : "memory");
}
__device__ __forceinline__ float dot4(float4 a, float4 b) {
    return a.x*b.x + a.y*b.y + a.z*b.z + a.w*b.w;
}

// ---------------------------------------------------------------------------
// Launch 1: one warp per sample. Read x row + gathered center row; RED x row
// into g_sums (unconditional — no count prepass needed); warp-reduce Q, D, E
// and RED {Q, D, E, 1} into g_scal.
// ---------------------------------------------------------------------------
__global__ __launch_bounds__(THREADS) void accum(const float* __restrict__ x,
                                                 const float* __restrict__ center,
                                                 const int* __restrict__ label) {
    int w    = (blockIdx.x * THREADS + threadIdx.x) >> 5;   // sample id
    int lane = threadIdx.x & 31;
    int c    = label[w];                                    // broadcast load

    const float4* xr = reinterpret_cast<const float4*>(x)      + (size_t)w * F4;
    const float4* cr = reinterpret_cast<const float4*>(center) + (size_t)c * F4;
    float4 v0 = xr[lane], v1 = xr[lane + 32];
    float4 c0 = cr[lane], c1 = cr[lane + 32];

    // Fire the row REDs immediately (independent of the shuffle chains below).
    float* srow = reinterpret_cast<float*>(g_sums + (size_t)c * F4);
    red_add_v4(srow + lane * 4,        v0);
    red_add_v4(srow + (lane + 32) * 4, v1);

    float q = dot4(v0, v0) + dot4(v1, v1);
    float d = dot4(v0, c0) + dot4(v1, c1);
    float e = dot4(c0, c0) + dot4(c1, c1);
    #pragma unroll
    for (int o = 16; o > 0; o >>= 1) {
        q += __shfl_down_sync(0xFFFFFFFFu, q, o);
        d += __shfl_down_sync(0xFFFFFFFFu, d, o);
        e += __shfl_down_sync(0xFFFFFFFFu, e, o);
    }
    if (lane == 0) {
        float* base = reinterpret_cast<float*>(&g_scal[c]);
        red_add_f32(base + 0, q);
        red_add_f32(base + 1, d);
        red_add_f32(base + 2, e);
        red_add_f32(base + 3, 1.0f);
    }
}

// ---------------------------------------------------------------------------
// Launch 2: coalesced scan of g_scal -> per-class contribution. Compact all
// touched classes; n=1 rows are zero-stored blind (||s||^2 == Q), n>=2 rows
// are read for ||s||^2 then zeroed. g_loss atomic + last-block writes d_out
// and resets. All zero invariants restored.
// ---------------------------------------------------------------------------
__global__ __launch_bounds__(THREADS) void classpass(float* __restrict__ out) {
    __shared__ int   s_m;
    __shared__ int   s_cls[CPB];                // packed: (class << 1) | (n>=2)
    __shared__ float s_n[CPB];
    __shared__ float s_wsum[WPB];

    int tid  = threadIdx.x;
    int lane = tid & 31;
    int wid  = tid >> 5;

    if (tid == 0) s_m = 0;
    __syncthreads();

    float contrib = 0.f;
    int c = blockIdx.x * CPB + tid;
    if (c < NC) {
        float4 sc = g_scal[c];                  // coalesced 16B
        if (sc.w > 0.f) {
            contrib = sc.x - A_D * sc.y + A_E * sc.z;
            bool multi = (sc.w != 1.f);
            if (!multi) contrib -= A_S * sc.x;  // ||s||^2 == Q for n = 1
            int p = atomicAdd(&s_m, 1);
            s_cls[p] = (c << 1) | (multi ? 1 : 0);
            s_n[p]   = sc.w;
            g_scal[c] = make_float4(0.f, 0.f, 0.f, 0.f);    // restore invariant
        }
    }
    __syncthreads();

    int m = s_m;                                // ~40 touched classes per block
    float4 z = make_float4(0.f, 0.f, 0.f, 0.f);
    for (int i = wid; i < m; i += WPB) {
        int pk = s_cls[i];
        int cc = pk >> 1;
        float4* srow = g_sums + (size_t)cc * F4;
        if (pk & 1) {                           // multi: read, reduce, zero
            float4 s0 = srow[lane], s1 = srow[lane + 32];
            srow[lane] = z;
            srow[lane + 32] = z;
            float ss = dot4(s0, s0) + dot4(s1, s1);
            #pragma unroll
            for (int o = 16; o > 0; o >>= 1)
                ss += __shfl_down_sync(0xFFFFFFFFu, ss, o);
            if (lane == 0) contrib -= A_S * ss / s_n[i];
        } else {                                // n=1: blind zero-store only
            srow[lane] = z;
            srow[lane + 32] = z;
        }
    }

    #pragma unroll
    for (int o = 16; o > 0; o >>= 1)
        contrib += __shfl_down_sync(0xFFFFFFFFu, contrib, o);
    if (lane == 0) s_wsum[wid] = contrib;
    __syncthreads();

    if (tid == 0) {
        float b = 0.f;
        #pragma unroll
        for (int i = 0; i < WPB; i++) b += s_wsum[i];
        atomicAdd(&g_loss, b);                  // 391 ops, one addr: negligible
        __threadfence();
        if (atomicAdd(&g_done, 1u) == (unsigned)(gridDim.x - 1)) {
            out[0] = __ldcg(&g_loss) * (1.f / ((float)BATCH * (float)FEAT));
            g_loss = 0.f;                       // restore invariants
            g_done = 0u;
        }
    }
}

extern "C" void kernel_launch(void* const* d_in, const int* in_sizes, int n_in,
                              void* d_out, int out_size) {
    const float* x      = (const float*)d_in[0];   // batch_feature [16384, 256] f32
    const int*   label  = (const int*)d_in[1];     // batch_label   [16384] int32
    const float* center = (const float*)d_in[2];   // center_feature[100000, 256] f32
    float* out = (float*)d_out;

    accum    <<<ACC_BLOCKS, THREADS>>>(x, center, label);
    classpass<<<CLS_BLOCKS, THREADS>>>(out);
}

// round 12
// speedup vs baseline: 1.4411x; 1.3409x over previous
#include <cuda_runtime.h>
#include <cstdint>

#define NC         100000
#define FEAT       256
#define BATCH      16384
#define F4         64                          // FEAT / 4
#define THREADS    256
#define WPB        8
#define ACC_BLOCKS (BATCH / WPB)               // 2048 (one warp per sample)
#define CPB        256                         // classes scanned per block
#define CLS_BLOCKS ((NC + CPB - 1) / CPB)      // 391

// contrib_c = Q - 1.9602 D + 0.9801 E - (0.0199/n) ||s||^2
//   Q = sum ||x_i||^2, D = c.s, E = n ||c||^2   (t = 0.99c + 0.01 s/n)
#define A_D 1.9602f
#define A_E 0.9801f
#define A_S 0.0199f

// Scratch — zero at module load; every replay restores the all-zero invariant.
// (g_next needs no invariant: every slot is unconditionally overwritten.)
__device__ float4   g_scal[NC];      // {Q, D, E, n}  (1.6 MB)
__device__ int      g_head[NC];      // linked-list head, idx+1 encoded (0 = empty)
__device__ int      g_next[BATCH];
__device__ float    g_loss;
__device__ unsigned g_done;

__device__ __forceinline__ void red_add_f32(float* addr, float v) {
    asm volatile("red.global.add.f32 [%0], %1;" :: "l"(addr), "f"(v) : "memory");
}
__device__ __forceinline__ float dot4(float4 a, float4 b) {
    return a.x*b.x + a.y*b.y + a.z*b.z + a.w*b.w;
}
__device__ __forceinline__ void add4(float4& a, float4 b) {
    a.x += b.x; a.y += b.y; a.z += b.z; a.w += b.w;
}

// ---------------------------------------------------------------------------
// Launch 1: one warp per sample. Read x row + gathered center row; warp-
// reduce Q, D, E; lane 0 REDs {Q,D,E,1} into g_scal and pushes the sample
// onto its class's linked list (spread atomics, ~n<=5 contention per class).
// ---------------------------------------------------------------------------
__global__ __launch_bounds__(THREADS) void accum(const float* __restrict__ x,
                                                 const float* __restrict__ center,
                                                 const int* __restrict__ label) {
    int w    = (blockIdx.x * THREADS + threadIdx.x) >> 5;   // sample id
    int lane = threadIdx.x & 31;
    int c    = label[w];                                    // broadcast load

    const float4* xr = reinterpret_cast<const float4*>(x)      + (size_t)w * F4;
    const float4* cr = reinterpret_cast<const float4*>(center) + (size_t)c * F4;
    float4 v0 = xr[lane], v1 = xr[lane + 32];
    float4 c0 = cr[lane], c1 = cr[lane + 32];

    float q = dot4(v0, v0) + dot4(v1, v1);
    float d = dot4(v0, c0) + dot4(v1, c1);
    float e = dot4(c0, c0) + dot4(c1, c1);
    #pragma unroll
    for (int o = 16; o > 0; o >>= 1) {
        q += __shfl_down_sync(0xFFFFFFFFu, q, o);
        d += __shfl_down_sync(0xFFFFFFFFu, d, o);
        e += __shfl_down_sync(0xFFFFFFFFu, e, o);
    }
    if (lane == 0) {
        g_next[w] = atomicExch(&g_head[c], w + 1);          // list push
        float* base = reinterpret_cast<float*>(&g_scal[c]);
        red_add_f32(base + 0, q);
        red_add_f32(base + 1, d);
        red_add_f32(base + 2, e);
        red_add_f32(base + 3, 1.0f);
    }
}

// ---------------------------------------------------------------------------
// Launch 2: coalesced scan of g_scal. n=1 classes close with ||s||^2 == Q.
// Multi classes (n>=2, ~1.2K total) get a warp that walks the class's linked
// list, accumulates s in registers, and computes ||s||^2 — no per-class row
// storage anywhere. g_loss atomic + last-block writes d_out. All invariants
// (scal, head, loss, done) restored.
// ---------------------------------------------------------------------------
__global__ __launch_bounds__(THREADS) void classpass(const float* __restrict__ x,
                                                     float* __restrict__ out) {
    __shared__ int   s_m;
    __shared__ int   s_head[CPB];
    __shared__ float s_n[CPB];
    __shared__ float s_wsum[WPB];

    int tid  = threadIdx.x;
    int lane = tid & 31;
    int wid  = tid >> 5;

    if (tid == 0) s_m = 0;
    __syncthreads();

    float contrib = 0.f;
    int c = blockIdx.x * CPB + tid;
    if (c < NC) {
        float4 sc = g_scal[c];                  // coalesced 16B
        if (sc.w > 0.f) {
            contrib = sc.x - A_D * sc.y + A_E * sc.z;
            if (sc.w == 1.f) {
                contrib -= A_S * sc.x;          // ||s||^2 == Q for n = 1
            } else {
                int p = atomicAdd(&s_m, 1);     // smem atomic
                s_head[p] = g_head[c];          // capture before reset
                s_n[p]    = sc.w;
            }
            g_scal[c] = make_float4(0.f, 0.f, 0.f, 0.f);    // restore invariant
            g_head[c] = 0;
        }
    }
    __syncthreads();

    int m = s_m;                                // ~3 multi classes per block
    for (int i = wid; i < m; i += WPB) {
        float4 a0 = make_float4(0.f, 0.f, 0.f, 0.f);
        float4 a1 = make_float4(0.f, 0.f, 0.f, 0.f);
        int a = s_head[i] - 1;
        while (a >= 0) {                        // walk the n-sample chain
            int nx = g_next[a];                 // broadcast; issues early
            const float4* xr = reinterpret_cast<const float4*>(x) + (size_t)a * F4;
            add4(a0, xr[lane]);
            add4(a1, xr[lane + 32]);
            a = nx - 1;
        }
        float ss = dot4(a0, a0) + dot4(a1, a1);
        #pragma unroll
        for (int o = 16; o > 0; o >>= 1)
            ss += __shfl_down_sync(0xFFFFFFFFu, ss, o);
        if (lane == 0) contrib -= A_S * ss / s_n[i];
    }

    #pragma unroll
    for (int o = 16; o > 0; o >>= 1)
        contrib += __shfl_down_sync(0xFFFFFFFFu, contrib, o);
    if (lane == 0) s_wsum[wid] = contrib;
    __syncthreads();

    if (tid == 0) {
        float b = 0.f;
        #pragma unroll
        for (int i = 0; i < WPB; i++) b += s_wsum[i];
        atomicAdd(&g_loss, b);                  // 391 ops, one addr: negligible
        __threadfence();
        if (atomicAdd(&g_done, 1u) == (unsigned)(gridDim.x - 1)) {
            out[0] = __ldcg(&g_loss) * (1.f / ((float)BATCH * (float)FEAT));
            g_loss = 0.f;                       // restore invariants
            g_done = 0u;
        }
    }
}

extern "C" void kernel_launch(void* const* d_in, const int* in_sizes, int n_in,
                              void* d_out, int out_size) {
    const float* x      = (const float*)d_in[0];   // batch_feature [16384, 256] f32
    const int*   label  = (const int*)d_in[1];     // batch_label   [16384] int32
    const float* center = (const float*)d_in[2];   // center_feature[100000, 256] f32
    float* out = (float*)d_out;

    accum    <<<ACC_BLOCKS, THREADS>>>(x, center, label);
    classpass<<<CLS_BLOCKS, THREADS>>>(x, out);
}